// round 13
// baseline (speedup 1.0000x reference)
#include <cuda_runtime.h>
#include <cuda_bf16.h>

#define BB 2
#define CC 256
#define LL 4096
#define NN 16
#define RR 64
#define NH 4    // n-values per thread (n split across lane quads)
#define CN (CC*NN)

typedef unsigned long long u64;

// ---------------- static device scratch (no allocations) ----------------
__device__ float4 g_A4   [CC*NN/4];          // A2 = -exp(A_log)*log2(e), (c,n)
__device__ float2 g_du   [BB*LL*CC];         // (delta, delta*x) packed
__device__ float4 g_Bm4  [BB*LL*NN/4];       // (b,p,n)
__device__ float4 g_Cm4  [BB*LL*NN/4];
__device__ float  g_rs   [BB*RR*CC];         // row delta sums
__device__ float  g_cs   [BB*RR*CC];         // col delta sums
__device__ float4 g_ef4  [BB*RR*CC*NN/4];    // row fwd local end states
__device__ float4 g_eb4  [BB*RR*CC*NN/4];    // row bwd local end states
__device__ float4 g_ec4  [BB*RR*CC*NN/4];    // col fwd local end states
__device__ float4 g_c14  [BB*RR*CC*NN/4];    // carries per chunk, dir 1..4
__device__ float4 g_c24  [BB*RR*CC*NN/4];
__device__ float4 g_c34  [BB*RR*CC*NN/4];
__device__ float4 g_c44  [BB*RR*CC*NN/4];
__device__ float  g_y13  [BB*LL*CC];         // y1+y3
__device__ float  g_y2   [BB*LL*CC];         // y2
__device__ float  g_y4   [BB*LL*CC];         // y4

__device__ __forceinline__ float ex2f(float x) {
    float r; asm("ex2.approx.f32 %0, %1;" : "=f"(r) : "f"(x)); return r;
}
__device__ __forceinline__ u64 pk2(float lo, float hi) {
    u64 r; asm("mov.b64 %0, {%1, %2};" : "=l"(r) : "f"(lo), "f"(hi)); return r;
}
__device__ __forceinline__ void up2(u64 v, float& lo, float& hi) {
    asm("mov.b64 {%0, %1}, %2;" : "=f"(lo), "=f"(hi) : "l"(v));
}
#define FMA2(d,a,b,c) asm("fma.rn.f32x2 %0, %1, %2, %3;" : "=l"(d) : "l"(a), "l"(b), "l"(c))
#define MUL2(d,a,b)   asm("mul.rn.f32x2 %0, %1, %2;"     : "=l"(d) : "l"(a), "l"(b))
#define ADD2(d,a,b)   asm("add.rn.f32x2 %0, %1, %2;"     : "=l"(d) : "l"(a), "l"(b))

__device__ __forceinline__ void split_tf32(float x, unsigned& hi, unsigned& lo) {
    unsigned h; asm("cvt.rna.tf32.f32 %0, %1;" : "=r"(h) : "f"(x));
    float hf = __uint_as_float(h);
    float l = x - hf;
    unsigned lw; asm("cvt.rna.tf32.f32 %0, %1;" : "=r"(lw) : "f"(l));
    hi = h; lo = lw;
}

#define MMA8(acc, a, bq) asm volatile( \
  "mma.sync.aligned.m16n8k8.row.col.f32.tf32.tf32.f32 " \
  "{%0,%1,%2,%3},{%4,%5,%6,%7},{%8,%9},{%0,%1,%2,%3};\n" \
  : "+f"(acc[0]),"+f"(acc[1]),"+f"(acc[2]),"+f"(acc[3]) \
  : "r"(a[0]),"r"(a[1]),"r"(a[2]),"r"(a[3]), "r"(bq[0]),"r"(bq[1]))

__device__ __forceinline__ float softplusf(float xw) {
    return (xw > 0.f) ? xw + log1pf(__expf(-xw)) : log1pf(__expf(xw));
}

// ---------------- fused GEMM (tensor cores, tf32 compensated) ----------------
__global__ void __launch_bounds__(256, 2) k_gemm_tc(
    const float* __restrict__ F,
    const float* __restrict__ Wd,
    const float* __restrict__ bd,
    const float* __restrict__ WB,
    const float* __restrict__ WC,
    const float* __restrict__ A_log)
{
    __shared__ float As[2][16][132];
    __shared__ float Bs[2][16][68];
    int t = threadIdx.x;
    bool isBC = (blockIdx.y == 4);
    if (isBC && blockIdx.x < 16) {
        int i = blockIdx.x * 256 + t;
        ((float*)g_A4)[i] = -expf(A_log[i]) * 1.4426950408889634f;
    }
    int m0 = blockIdx.x * 128;
    int n0 = blockIdx.y * 64;
    int b = m0 / LL;
    int pbase = m0 % LL;
    int warp = t >> 5, lane = t & 31;
    int wm = warp >> 1, wn = warp & 1;
    int lr = lane >> 2, lc = lane & 3;

    const float* Fb = F + (size_t)b*CC*LL + pbase;
    float acc[2][4][4] = {};

    auto stage = [&](int chunk, int buf) {
        int k0 = chunk * 16;
        #pragma unroll
        for (int i = 0; i < 2; i++) {
            int s = t + i*256;
            int k = s >> 5, m4 = (s & 31) << 2;
            unsigned dst = (unsigned)__cvta_generic_to_shared(&As[buf][k][m4]);
            const float* src = Fb + (size_t)(k0+k)*LL + m4;
            asm volatile("cp.async.cg.shared.global [%0], [%1], 16;\n" :: "r"(dst), "l"(src));
        }
        {
            int s = t;
            int k = s >> 4, n4 = (s & 15) << 2;
            unsigned dst = (unsigned)__cvta_generic_to_shared(&Bs[buf][k][n4]);
            if (!isBC) {
                const float* src = Wd + (size_t)(k0+k)*CC + n0 + n4;
                asm volatile("cp.async.cg.shared.global [%0], [%1], 16;\n" :: "r"(dst), "l"(src));
            } else {
                const float* src = (n4 < 16) ? (WB + (size_t)(k0+k)*16 + n4)
                                 : (n4 < 32) ? (WC + (size_t)(k0+k)*16 + (n4-16))
                                             : WB;
                int sz = (n4 < 32) ? 16 : 0;
                asm volatile("cp.async.cg.shared.global [%0], [%1], 16, %2;\n"
                             :: "r"(dst), "l"(src), "r"(sz));
            }
        }
        asm volatile("cp.async.commit_group;\n");
    };

    stage(0, 0);
    for (int chunk = 0; chunk < 16; chunk++) {
        int buf = chunk & 1;
        if (chunk < 15) {
            stage(chunk+1, buf^1);
            asm volatile("cp.async.wait_group 1;\n");
        } else {
            asm volatile("cp.async.wait_group 0;\n");
        }
        __syncthreads();
        #pragma unroll
        for (int kk = 0; kk < 16; kk += 8) {
            unsigned ah[2][4], al[2][4], bh[4][2], bl[4][2];
            #pragma unroll
            for (int mt = 0; mt < 2; mt++) {
                int row = wm*32 + mt*16 + lr;
                split_tf32(As[buf][kk+lc][row],     ah[mt][0], al[mt][0]);
                split_tf32(As[buf][kk+lc][row+8],   ah[mt][1], al[mt][1]);
                split_tf32(As[buf][kk+4+lc][row],   ah[mt][2], al[mt][2]);
                split_tf32(As[buf][kk+4+lc][row+8], ah[mt][3], al[mt][3]);
            }
            #pragma unroll
            for (int nt = 0; nt < 4; nt++) {
                int n = wn*32 + nt*8 + lr;
                split_tf32(Bs[buf][kk+lc][n],   bh[nt][0], bl[nt][0]);
                split_tf32(Bs[buf][kk+4+lc][n], bh[nt][1], bl[nt][1]);
            }
            #pragma unroll
            for (int mt = 0; mt < 2; mt++)
                #pragma unroll
                for (int nt = 0; nt < 4; nt++) {
                    MMA8(acc[mt][nt], ah[mt], bh[nt]);
                    MMA8(acc[mt][nt], ah[mt], bl[nt]);
                    MMA8(acc[mt][nt], al[mt], bh[nt]);
                }
        }
        __syncthreads();
    }

    if (!isBC) {
        #pragma unroll
        for (int mt = 0; mt < 2; mt++) {
            int m_lo = wm*32 + mt*16 + lr;
            #pragma unroll
            for (int nt = 0; nt < 4; nt++) {
                int n = n0 + wn*32 + nt*8 + lc*2;
                float b0 = bd[n], b1 = bd[n+1];
                #pragma unroll
                for (int h = 0; h < 2; h++) {
                    int m = m_lo + h*8;
                    size_t mg = (size_t)m0 + m;
                    float sp0 = softplusf(acc[mt][nt][h*2+0] + b0);
                    float sp1 = softplusf(acc[mt][nt][h*2+1] + b1);
                    float x0 = Fb[(size_t)n*LL + m];
                    float x1 = Fb[(size_t)(n+1)*LL + m];
                    g_du[mg*CC + n]     = make_float2(sp0, sp0*x0);
                    g_du[mg*CC + n + 1] = make_float2(sp1, sp1*x1);
                }
            }
        }
    } else {
        float* gBm = (float*)g_Bm4;
        float* gCm = (float*)g_Cm4;
        #pragma unroll
        for (int mt = 0; mt < 2; mt++) {
            int m_lo = wm*32 + mt*16 + lr;
            #pragma unroll
            for (int nt = 0; nt < 4; nt++) {
                int nl = wn*32 + nt*8 + lc*2;
                if (nl >= 32) continue;
                #pragma unroll
                for (int h = 0; h < 2; h++) {
                    int m = m_lo + h*8;
                    size_t mg = (size_t)m0 + m;
                    float v0 = acc[mt][nt][h*2+0];
                    float v1 = acc[mt][nt][h*2+1];
                    if (nl < 16) {
                        gBm[mg*NN + nl]     = v0;
                        gBm[mg*NN + nl + 1] = v1;
                    } else {
                        gCm[mg*NN + nl - 16] = v0;
                        gCm[mg*NN + nl - 15] = v1;
                    }
                }
            }
        }
    }
}

// ---------------- pass1: per-chunk local end states + delta sums (f32x2) ----------------
__global__ void __launch_bounds__(256) k_pass1() {
    int blk = blockIdx.x;
    bool isCol = blk >= BB*RR*4;
    int bid = isCol ? blk - BB*RR*4 : blk;
    int b = bid / (RR*4);
    int rem = bid % (RR*4);
    int chunk = rem >> 2;
    int cg = rem & 3;
    int q = threadIdx.x & 3;
    int c = cg*64 + (threadIdx.x >> 2);

    float4 a0 = g_A4[c*4 + q];
    u64 A2p0 = pk2(a0.x, a0.y), A2p1 = pk2(a0.z, a0.w);

    if (!isCol) {
        u64 ef0 = 0, ef1 = 0, eb0 = 0, eb1 = 0;
        u64 Pp0 = pk2(1.f, 1.f), Pp1 = pk2(1.f, 1.f);
        float rs = 0.f;
        int pbase = chunk*64;
        const float2* pDu = g_du + ((size_t)(b*LL + pbase))*CC + c;
        const float4* pBm = g_Bm4 + (b*LL + pbase)*4 + q;
        #pragma unroll 4
        for (int ts = 0; ts < 64; ts++) {
            float2 du = *pDu;
            float4 v = *pBm;
            rs += du.x;
            u64 dd = pk2(du.x, du.x), uu = pk2(du.y, du.y);
            u64 t0, t1; MUL2(t0, dd, A2p0); MUL2(t1, dd, A2p1);
            float x0,x1,x2,x3; up2(t0,x0,x1); up2(t1,x2,x3);
            u64 a01 = pk2(ex2f(x0), ex2f(x1));
            u64 a23 = pk2(ex2f(x2), ex2f(x3));
            u64 bm01 = pk2(v.x, v.y), bm23 = pk2(v.z, v.w);
            u64 w0, w1; MUL2(w0, uu, bm01); MUL2(w1, uu, bm23);
            FMA2(eb0, w0, Pp0, eb0); FMA2(eb1, w1, Pp1, eb1);
            MUL2(Pp0, Pp0, a01);     MUL2(Pp1, Pp1, a23);
            FMA2(ef0, a01, ef0, w0); FMA2(ef1, a23, ef1, w1);
            pDu += CC; pBm += 4;
        }
        int i4 = ((b*RR + chunk)*CC + c)*4 + q;
        float e0,e1,e2,e3; up2(ef0,e0,e1); up2(ef1,e2,e3);
        g_ef4[i4] = make_float4(e0,e1,e2,e3);
        up2(eb0,e0,e1); up2(eb1,e2,e3);
        g_eb4[i4] = make_float4(e0,e1,e2,e3);
        if (q == 0) g_rs[(b*RR + chunk)*CC + c] = rs;
    } else {
        u64 ec0 = 0, ec1 = 0;
        float cs = 0.f;
        const float2* pDu = g_du + ((size_t)(b*LL + chunk))*CC + c;
        const float4* pBm = g_Bm4 + (b*LL + chunk)*4 + q;
        #pragma unroll 4
        for (int h = 0; h < 64; h++) {
            float2 du = *pDu;
            float4 v = *pBm;
            cs += du.x;
            u64 dd = pk2(du.x, du.x), uu = pk2(du.y, du.y);
            u64 t0, t1; MUL2(t0, dd, A2p0); MUL2(t1, dd, A2p1);
            float x0,x1,x2,x3; up2(t0,x0,x1); up2(t1,x2,x3);
            u64 a01 = pk2(ex2f(x0), ex2f(x1));
            u64 a23 = pk2(ex2f(x2), ex2f(x3));
            u64 bm01 = pk2(v.x, v.y), bm23 = pk2(v.z, v.w);
            u64 w0, w1; MUL2(w0, uu, bm01); MUL2(w1, uu, bm23);
            FMA2(ec0, a01, ec0, w0); FMA2(ec1, a23, ec1, w1);
            pDu += 64*CC; pBm += 256;
        }
        int i4 = ((b*RR + chunk)*CC + c)*4 + q;
        float e0,e1,e2,e3; up2(ec0,e0,e1); up2(ec1,e2,e3);
        g_ec4[i4] = make_float4(e0,e1,e2,e3);
        if (q == 0) g_cs[(b*RR + chunk)*CC + c] = cs;
    }
}

// ---------------- mid: carry scans, smem-transposed + warp Kogge-Stone ----------------
__global__ void __launch_bounds__(256) k_mid_t() {
    __shared__ float2 tA[32][33];
    __shared__ float2 tB[32][33];
    __shared__ float rs_sm[2][64];

    int t = threadIdx.x;
    int warp = t >> 5, lane = t & 31;
    int which = blockIdx.y;
    int g0 = blockIdx.x * 32;
    int b = g0 / CN;
    int cn0 = g0 % CN;
    int cbase = cn0 >> 4;
    const unsigned FULL = 0xffffffffu;

    const float* grs = (which == 2) ? g_cs : g_rs;
    if (t < 128) {
        int r = t & 63, cl = t >> 6;
        rs_sm[cl][r] = grs[(b*RR + r)*CC + cbase + cl];
    }
    const float* eA = (which == 0) ? (const float*)g_ef4
                    : (which == 1) ? (const float*)g_eb4
                                   : (const float*)g_ec4;
    #pragma unroll
    for (int i = 0; i < 8; i++) {
        int r = warp*8 + i;
        size_t src = (size_t)(b*RR + r)*CN + cn0 + lane;
        ((float*)&tA[lane][0])[r] = eA[src];
        if (which == 1)
            ((float*)&tB[lane][0])[r] = ((const float*)g_ef4)[src];
    }
    __syncthreads();

    #pragma unroll
    for (int k = 0; k < 4; k++) {
        int cnl = warp*4 + k;
        float A2v = ((const float*)g_A4)[cn0 + cnl];
        int cl = cnl >> 4;

        if (which == 0) {
            float2 e = tA[cnl][lane];
            float e0 = e.x, e1 = e.y;
            float G0 = ex2f(A2v * rs_sm[cl][2*lane]);
            float G1 = ex2f(A2v * rs_sm[cl][2*lane+1]);
            float a  = G0 * G1;
            float bv = fmaf(G1, e0, e1);
            #pragma unroll
            for (int off = 1; off < 32; off <<= 1) {
                float pa = __shfl_up_sync(FULL, a, off);
                float pb = __shfl_up_sync(FULL, bv, off);
                if (lane >= off) { bv = fmaf(a, pb, bv); a *= pa; }
            }
            float xb = __shfl_up_sync(FULL, bv, 1);
            if (lane == 0) xb = 0.f;
            tA[cnl][lane] = make_float2(xb, fmaf(G0, xb, e0));
        } else {
            int slot = 31 - lane;
            float2 e = tA[cnl][slot];
            float e0 = e.y, e1 = e.x;
            float G0 = ex2f(A2v * rs_sm[cl][63 - 2*lane]);
            float G1 = ex2f(A2v * rs_sm[cl][62 - 2*lane]);
            float a  = G0 * G1;
            float bv = fmaf(G1, e0, e1);
            if (which == 1) {
                float2 e3 = tB[cnl][slot];
                float f0 = e3.y, f1 = e3.x;
                float b3 = fmaf(G1, f0, f1);
                float a2 = a;
                #pragma unroll
                for (int off = 1; off < 32; off <<= 1) {
                    float pa  = __shfl_up_sync(FULL, a2, off);
                    float pb2 = __shfl_up_sync(FULL, bv, off);
                    float pb3 = __shfl_up_sync(FULL, b3, off);
                    if (lane >= off) {
                        bv = fmaf(a2, pb2, bv);
                        b3 = fmaf(a2, pb3, b3);
                        a2 *= pa;
                    }
                }
                float xb2 = __shfl_up_sync(FULL, bv, 1);
                float xb3 = __shfl_up_sync(FULL, b3, 1);
                if (lane == 0) { xb2 = 0.f; xb3 = 0.f; }
                tA[cnl][slot] = make_float2(fmaf(G0, xb2, e0), xb2);
                tB[cnl][slot] = make_float2(fmaf(G0, xb3, f0), xb3);
            } else {
                #pragma unroll
                for (int off = 1; off < 32; off <<= 1) {
                    float pa = __shfl_up_sync(FULL, a, off);
                    float pb = __shfl_up_sync(FULL, bv, off);
                    if (lane >= off) { bv = fmaf(a, pb, bv); a *= pa; }
                }
                float xb = __shfl_up_sync(FULL, bv, 1);
                if (lane == 0) xb = 0.f;
                tA[cnl][slot] = make_float2(fmaf(G0, xb, e0), xb);
            }
        }
    }
    __syncthreads();

    float* oA = (which == 0) ? (float*)g_c14
              : (which == 1) ? (float*)g_c24
                             : (float*)g_c44;
    #pragma unroll
    for (int i = 0; i < 8; i++) {
        int r = warp*8 + i;
        size_t dst = (size_t)(b*RR + r)*CN + cn0 + lane;
        oA[dst] = ((float*)&tA[lane][0])[r];
        if (which == 1)
            ((float*)g_c34)[dst] = ((float*)&tB[lane][0])[r];
    }
}

// ---------------- pass2: local scans with carries, emit y (f32x2) ----------------
__global__ void __launch_bounds__(256) k_pass2() {
    int blk = blockIdx.x;
    int q = threadIdx.x & 3;

    if (blk < BB*RR*8) {
        int b = blk / (RR*8);
        int rem = blk % (RR*8);
        int chunk = rem >> 3;
        int cg = rem & 7;
        int warp = threadIdx.x >> 5;
        int wd = warp >> 2;                      // 0 = asc, 1 = desc
        int wi = warp & 3;
        int c = cg*32 + wi*8 + ((threadIdx.x & 31) >> 2);

        float4 a0 = g_A4[c*4 + q];
        u64 A2p0 = pk2(a0.x, a0.y), A2p1 = pk2(a0.z, a0.w);
        int i4 = ((b*RR + chunk)*CC + c)*4 + q;
        int pbase = chunk*64;

        if (wd == 0) {
            u64 h1p0, h1p1, h3p0, h3p1;
            {
                float4 v0 = g_c14[i4];
                h1p0 = pk2(v0.x, v0.y); h1p1 = pk2(v0.z, v0.w);
                float4 w0 = g_c34[i4];
                h3p0 = pk2(w0.x, w0.y); h3p1 = pk2(w0.z, w0.w);
            }
            size_t ia0 = ((size_t)(b*LL + pbase))*CC + c;
            const float2* pDu = g_du + ia0;
            const float4* pBm = g_Bm4 + (b*LL + pbase)*4 + q;
            const float4* pCm = g_Cm4 + (b*LL + pbase)*4 + q;
            float* pY = g_y13 + ia0;
            #pragma unroll 4
            for (int i = 0; i < 64; i++) {
                float2 du = *pDu;
                float4 v = *pBm;
                float4 u = *pCm;
                u64 dd = pk2(du.x, du.x), uu = pk2(du.y, du.y);
                u64 t0, t1; MUL2(t0, dd, A2p0); MUL2(t1, dd, A2p1);
                float x0,x1,x2,x3; up2(t0,x0,x1); up2(t1,x2,x3);
                u64 a01 = pk2(ex2f(x0), ex2f(x1));
                u64 a23 = pk2(ex2f(x2), ex2f(x3));
                u64 bm01 = pk2(v.x, v.y), bm23 = pk2(v.z, v.w);
                u64 w0, w1; MUL2(w0, uu, bm01); MUL2(w1, uu, bm23);
                FMA2(h1p0, a01, h1p0, w0); FMA2(h1p1, a23, h1p1, w1);
                FMA2(h3p0, a01, h3p0, w0); FMA2(h3p1, a23, h3p1, w1);
                u64 s0, s1; ADD2(s0, h1p0, h3p0); ADD2(s1, h1p1, h3p1);
                u64 cm01 = pk2(u.x, u.y), cm23 = pk2(u.z, u.w);
                u64 y0, y1; MUL2(y0, s0, cm01); FMA2(y1, s1, cm23, y0);
                float yl, yh; up2(y1, yl, yh);
                float y = yl + yh;
                y += __shfl_xor_sync(0xffffffffu, y, 1);
                y += __shfl_xor_sync(0xffffffffu, y, 2);
                if (q == 0) *pY = y;
                pDu += CC; pBm += 4; pCm += 4; pY += CC;
            }
        } else {
            u64 h2p0, h2p1;
            {
                float4 v0 = g_c24[i4];
                h2p0 = pk2(v0.x, v0.y); h2p1 = pk2(v0.z, v0.w);
            }
            size_t id0 = ((size_t)(b*LL + pbase + 63))*CC + c;
            const float2* pDu = g_du + id0;
            const float4* pBm = g_Bm4 + (b*LL + pbase + 63)*4 + q;
            const float4* pCm = g_Cm4 + (b*LL + pbase + 63)*4 + q;
            float* pY = g_y2 + id0;
            #pragma unroll 4
            for (int i = 0; i < 64; i++) {
                float2 du = *pDu;
                float4 v = *pBm;
                float4 u = *pCm;
                u64 dd = pk2(du.x, du.x), uu = pk2(du.y, du.y);
                u64 t0, t1; MUL2(t0, dd, A2p0); MUL2(t1, dd, A2p1);
                float x0,x1,x2,x3; up2(t0,x0,x1); up2(t1,x2,x3);
                u64 a01 = pk2(ex2f(x0), ex2f(x1));
                u64 a23 = pk2(ex2f(x2), ex2f(x3));
                u64 bm01 = pk2(v.x, v.y), bm23 = pk2(v.z, v.w);
                u64 w0, w1; MUL2(w0, uu, bm01); MUL2(w1, uu, bm23);
                FMA2(h2p0, a01, h2p0, w0); FMA2(h2p1, a23, h2p1, w1);
                u64 cm01 = pk2(u.x, u.y), cm23 = pk2(u.z, u.w);
                u64 y0, y1; MUL2(y0, h2p0, cm01); FMA2(y1, h2p1, cm23, y0);
                float yl, yh; up2(y1, yl, yh);
                float y = yl + yh;
                y += __shfl_xor_sync(0xffffffffu, y, 1);
                y += __shfl_xor_sync(0xffffffffu, y, 2);
                if (q == 0) *pY = y;
                pDu -= CC; pBm -= 4; pCm -= 4; pY -= CC;
            }
        }
    } else {
        int bid = blk - BB*RR*8;
        int b = bid / (RR*4);
        int rem = bid % (RR*4);
        int chunk = rem >> 2;                    // column index
        int cg = rem & 3;
        int c = cg*64 + (threadIdx.x >> 2);

        float4 a0 = g_A4[c*4 + q];
        u64 A2p0 = pk2(a0.x, a0.y), A2p1 = pk2(a0.z, a0.w);
        int i4 = ((b*RR + chunk)*CC + c)*4 + q;
        u64 h4p0, h4p1;
        {
            float4 v0 = g_c44[i4];
            h4p0 = pk2(v0.x, v0.y); h4p1 = pk2(v0.z, v0.w);
        }
        size_t i0 = ((size_t)(b*LL + chunk))*CC + c;
        const float2* pDu = g_du + i0;
        const float4* pBm = g_Bm4 + (b*LL + chunk)*4 + q;
        const float4* pCm = g_Cm4 + (b*LL + chunk)*4 + q;
        float* pY = g_y4 + i0;
        #pragma unroll 4
        for (int h = 0; h < 64; h++) {
            float2 du = *pDu;
            float4 v = *pBm;
            float4 u = *pCm;
            u64 dd = pk2(du.x, du.x), uu = pk2(du.y, du.y);
            u64 t0, t1; MUL2(t0, dd, A2p0); MUL2(t1, dd, A2p1);
            float x0,x1,x2,x3; up2(t0,x0,x1); up2(t1,x2,x3);
            u64 a01 = pk2(ex2f(x0), ex2f(x1));
            u64 a23 = pk2(ex2f(x2), ex2f(x3));
            u64 bm01 = pk2(v.x, v.y), bm23 = pk2(v.z, v.w);
            u64 w0, w1; MUL2(w0, uu, bm01); MUL2(w1, uu, bm23);
            FMA2(h4p0, a01, h4p0, w0); FMA2(h4p1, a23, h4p1, w1);
            u64 cm01 = pk2(u.x, u.y), cm23 = pk2(u.z, u.w);
            u64 y0, y1; MUL2(y0, h4p0, cm01); FMA2(y1, h4p1, cm23, y0);
            float yl, yh; up2(y1, yl, yh);
            float y = yl + yh;
            y += __shfl_xor_sync(0xffffffffu, y, 1);
            y += __shfl_xor_sync(0xffffffffu, y, 2);
            if (q == 0) *pY = y;
            pDu += 64*CC; pBm += 256; pCm += 256; pY += 64*CC;
        }
    }
}

// ---------------- final: combine 3 buffers, add x*D, transpose ----------------
__global__ void k_final(const float* __restrict__ F,
                        const float* __restrict__ Dv,
                        float* __restrict__ out)
{
    __shared__ float tile[32][33];
    int p0 = blockIdx.x * 32;
    int c0 = blockIdx.y * 32;
    int b = blockIdx.z;
    int tx = threadIdx.x, ty = threadIdx.y;   // (32, 8)
    #pragma unroll
    for (int i = 0; i < 4; i++) {
        int p = p0 + ty + i*8;
        size_t idx = ((size_t)(b*LL + p))*CC + c0 + tx;
        tile[ty + i*8][tx] = g_y13[idx] + g_y2[idx] + g_y4[idx];
    }
    __syncthreads();
    #pragma unroll
    for (int i = 0; i < 4; i++) {
        int cc = c0 + ty + i*8;
        int p = p0 + tx;
        size_t o = (size_t)b*CC*LL + (size_t)cc*LL + p;
        out[o] = 0.25f * tile[tx][ty + i*8] + F[o] * Dv[cc];
    }
}

// ---------------- launch ----------------
extern "C" void kernel_launch(void* const* d_in, const int* in_sizes, int n_in,
                              void* d_out, int out_size) {
    const float* F     = (const float*)d_in[0];
    const float* A_log = (const float*)d_in[1];
    const float* Dv    = (const float*)d_in[2];
    const float* Wd    = (const float*)d_in[3];
    const float* bd    = (const float*)d_in[4];
    const float* WB    = (const float*)d_in[5];
    const float* WC    = (const float*)d_in[6];
    float* out = (float*)d_out;

    {
        dim3 gd(BB*LL/128, 5);
        k_gemm_tc<<<gd, 256>>>(F, Wd, bd, WB, WC, A_log);
    }
    k_pass1<<<2*BB*RR*4, 256>>>();
    k_mid_t<<<dim3(BB*CN/32, 3), 256>>>();
    k_pass2<<<BB*RR*8 + BB*RR*4, 256>>>();
    k_final<<<dim3(LL/32, CC/32, BB), dim3(32, 8)>>>(F, Dv, out);
}

// round 14
// speedup vs baseline: 1.0671x; 1.0671x over previous
#include <cuda_runtime.h>
#include <cuda_bf16.h>

#define BB 2
#define CC 256
#define LL 4096
#define NN 16
#define RR 64
#define NH 4    // n-values per thread (n split across lane quads)
#define CN (CC*NN)

// ---------------- static device scratch (no allocations) ----------------
__device__ float4 g_A4   [CC*NN/4];          // A2 = -exp(A_log)*log2(e), (c,n)
__device__ float2 g_du   [BB*LL*CC];         // (delta, delta*x) packed
__device__ float4 g_Bm4  [BB*LL*NN/4];       // (b,p,n)
__device__ float4 g_Cm4  [BB*LL*NN/4];
__device__ float  g_rs   [BB*RR*CC];         // row delta sums
__device__ float  g_cs   [BB*RR*CC];         // col delta sums
__device__ float4 g_ef4  [BB*RR*CC*NN/4];    // row fwd local end states
__device__ float4 g_eb4  [BB*RR*CC*NN/4];    // row bwd local end states
__device__ float4 g_ec4  [BB*RR*CC*NN/4];    // col fwd local end states
__device__ float4 g_c14  [BB*RR*CC*NN/4];    // carries per chunk, dir 1..4
__device__ float4 g_c24  [BB*RR*CC*NN/4];
__device__ float4 g_c34  [BB*RR*CC*NN/4];
__device__ float4 g_c44  [BB*RR*CC*NN/4];
__device__ float  g_y13  [BB*LL*CC];         // y1+y3
__device__ float  g_y2   [BB*LL*CC];         // y2
__device__ float  g_y4   [BB*LL*CC];         // y4

__device__ __forceinline__ float ex2f(float x) {
    float r; asm("ex2.approx.f32 %0, %1;" : "=f"(r) : "f"(x)); return r;
}

__device__ __forceinline__ unsigned cvt_tf32(float x) {
    unsigned h; asm("cvt.rna.tf32.f32 %0, %1;" : "=r"(h) : "f"(x)); return h;
}
__device__ __forceinline__ void split_tf32(float x, unsigned& hi, unsigned& lo) {
    unsigned h; asm("cvt.rna.tf32.f32 %0, %1;" : "=r"(h) : "f"(x));
    float hf = __uint_as_float(h);
    float l = x - hf;
    unsigned lw; asm("cvt.rna.tf32.f32 %0, %1;" : "=r"(lw) : "f"(l));
    hi = h; lo = lw;
}

#define MMA8(acc, a, bq) asm volatile( \
  "mma.sync.aligned.m16n8k8.row.col.f32.tf32.tf32.f32 " \
  "{%0,%1,%2,%3},{%4,%5,%6,%7},{%8,%9},{%0,%1,%2,%3};\n" \
  : "+f"(acc[0]),"+f"(acc[1]),"+f"(acc[2]),"+f"(acc[3]) \
  : "r"(a[0]),"r"(a[1]),"r"(a[2]),"r"(a[3]), "r"(bq[0]),"r"(bq[1]))

__device__ __forceinline__ float softplusf(float xw) {
    return (xw > 0.f) ? xw + log1pf(__expf(-xw)) : log1pf(__expf(xw));
}

// ---------------- fused GEMM (tensor cores, tf32, B-side compensated) ----------------
// D = Ahi*(Bhi + Blo): residual error = Alo*B ~ 2.4e-4 rel (A-side tf32 rounding).
__global__ void __launch_bounds__(256, 2) k_gemm_tc(
    const float* __restrict__ F,
    const float* __restrict__ Wd,
    const float* __restrict__ bd,
    const float* __restrict__ WB,
    const float* __restrict__ WC,
    const float* __restrict__ A_log)
{
    __shared__ float As[2][16][132];
    __shared__ float Bs[2][16][68];
    int t = threadIdx.x;
    bool isBC = (blockIdx.y == 4);
    if (isBC && blockIdx.x < 16) {
        int i = blockIdx.x * 256 + t;
        ((float*)g_A4)[i] = -expf(A_log[i]) * 1.4426950408889634f;
    }
    int m0 = blockIdx.x * 128;
    int n0 = blockIdx.y * 64;
    int b = m0 / LL;
    int pbase = m0 % LL;
    int warp = t >> 5, lane = t & 31;
    int wm = warp >> 1, wn = warp & 1;
    int lr = lane >> 2, lc = lane & 3;

    const float* Fb = F + (size_t)b*CC*LL + pbase;
    float acc[2][4][4] = {};

    auto stage = [&](int chunk, int buf) {
        int k0 = chunk * 16;
        #pragma unroll
        for (int i = 0; i < 2; i++) {
            int s = t + i*256;
            int k = s >> 5, m4 = (s & 31) << 2;
            unsigned dst = (unsigned)__cvta_generic_to_shared(&As[buf][k][m4]);
            const float* src = Fb + (size_t)(k0+k)*LL + m4;
            asm volatile("cp.async.cg.shared.global [%0], [%1], 16;\n" :: "r"(dst), "l"(src));
        }
        {
            int s = t;
            int k = s >> 4, n4 = (s & 15) << 2;
            unsigned dst = (unsigned)__cvta_generic_to_shared(&Bs[buf][k][n4]);
            if (!isBC) {
                const float* src = Wd + (size_t)(k0+k)*CC + n0 + n4;
                asm volatile("cp.async.cg.shared.global [%0], [%1], 16;\n" :: "r"(dst), "l"(src));
            } else {
                const float* src = (n4 < 16) ? (WB + (size_t)(k0+k)*16 + n4)
                                 : (n4 < 32) ? (WC + (size_t)(k0+k)*16 + (n4-16))
                                             : WB;
                int sz = (n4 < 32) ? 16 : 0;
                asm volatile("cp.async.cg.shared.global [%0], [%1], 16, %2;\n"
                             :: "r"(dst), "l"(src), "r"(sz));
            }
        }
        asm volatile("cp.async.commit_group;\n");
    };

    stage(0, 0);
    for (int chunk = 0; chunk < 16; chunk++) {
        int buf = chunk & 1;
        if (chunk < 15) {
            stage(chunk+1, buf^1);
            asm volatile("cp.async.wait_group 1;\n");
        } else {
            asm volatile("cp.async.wait_group 0;\n");
        }
        __syncthreads();
        #pragma unroll
        for (int kk = 0; kk < 16; kk += 8) {
            unsigned ah[2][4], bh[4][2], bl[4][2];
            #pragma unroll
            for (int mt = 0; mt < 2; mt++) {
                int row = wm*32 + mt*16 + lr;
                ah[mt][0] = cvt_tf32(As[buf][kk+lc][row]);
                ah[mt][1] = cvt_tf32(As[buf][kk+lc][row+8]);
                ah[mt][2] = cvt_tf32(As[buf][kk+4+lc][row]);
                ah[mt][3] = cvt_tf32(As[buf][kk+4+lc][row+8]);
            }
            #pragma unroll
            for (int nt = 0; nt < 4; nt++) {
                int n = wn*32 + nt*8 + lr;
                split_tf32(Bs[buf][kk+lc][n],   bh[nt][0], bl[nt][0]);
                split_tf32(Bs[buf][kk+4+lc][n], bh[nt][1], bl[nt][1]);
            }
            #pragma unroll
            for (int mt = 0; mt < 2; mt++)
                #pragma unroll
                for (int nt = 0; nt < 4; nt++) {
                    MMA8(acc[mt][nt], ah[mt], bh[nt]);
                    MMA8(acc[mt][nt], ah[mt], bl[nt]);
                }
        }
        __syncthreads();
    }

    if (!isBC) {
        #pragma unroll
        for (int mt = 0; mt < 2; mt++) {
            int m_lo = wm*32 + mt*16 + lr;
            #pragma unroll
            for (int nt = 0; nt < 4; nt++) {
                int n = n0 + wn*32 + nt*8 + lc*2;
                float b0 = bd[n], b1 = bd[n+1];
                #pragma unroll
                for (int h = 0; h < 2; h++) {
                    int m = m_lo + h*8;
                    size_t mg = (size_t)m0 + m;
                    float sp0 = softplusf(acc[mt][nt][h*2+0] + b0);
                    float sp1 = softplusf(acc[mt][nt][h*2+1] + b1);
                    float x0 = Fb[(size_t)n*LL + m];
                    float x1 = Fb[(size_t)(n+1)*LL + m];
                    g_du[mg*CC + n]     = make_float2(sp0, sp0*x0);
                    g_du[mg*CC + n + 1] = make_float2(sp1, sp1*x1);
                }
            }
        }
    } else {
        float* gBm = (float*)g_Bm4;
        float* gCm = (float*)g_Cm4;
        #pragma unroll
        for (int mt = 0; mt < 2; mt++) {
            int m_lo = wm*32 + mt*16 + lr;
            #pragma unroll
            for (int nt = 0; nt < 4; nt++) {
                int nl = wn*32 + nt*8 + lc*2;
                if (nl >= 32) continue;
                #pragma unroll
                for (int h = 0; h < 2; h++) {
                    int m = m_lo + h*8;
                    size_t mg = (size_t)m0 + m;
                    float v0 = acc[mt][nt][h*2+0];
                    float v1 = acc[mt][nt][h*2+1];
                    if (nl < 16) {
                        gBm[mg*NN + nl]     = v0;
                        gBm[mg*NN + nl + 1] = v1;
                    } else {
                        gCm[mg*NN + nl - 16] = v0;
                        gCm[mg*NN + nl - 15] = v1;
                    }
                }
            }
        }
    }
}

// ---------------- pass1: per-chunk local end states + delta sums ----------------
__global__ void __launch_bounds__(256) k_pass1() {
    int blk = blockIdx.x;
    bool isCol = blk >= BB*RR*4;
    int bid = isCol ? blk - BB*RR*4 : blk;
    int b = bid / (RR*4);
    int rem = bid % (RR*4);
    int chunk = rem >> 2;
    int cg = rem & 3;
    int q = threadIdx.x & 3;
    int c = cg*64 + (threadIdx.x >> 2);

    float A2[NH];
    {
        float4 a0 = g_A4[c*4 + q];
        A2[0]=a0.x; A2[1]=a0.y; A2[2]=a0.z; A2[3]=a0.w;
    }

    if (!isCol) {
        float ef[NH], eb[NH], Pp[NH];
        #pragma unroll
        for (int n = 0; n < NH; n++) { ef[n]=0.f; eb[n]=0.f; Pp[n]=1.f; }
        float rs = 0.f;
        int pbase = chunk*64;
        const float2* pDu = g_du + ((size_t)(b*LL + pbase))*CC + c;
        const float4* pBm = g_Bm4 + (b*LL + pbase)*4 + q;
        #pragma unroll 4
        for (int ts = 0; ts < 64; ts++) {
            float2 du = *pDu;
            float4 v = *pBm;
            float d = du.x, uu = du.y;
            rs += d;
            float bm[NH] = {v.x, v.y, v.z, v.w};
            #pragma unroll
            for (int n = 0; n < NH; n++) {
                float a = ex2f(d * A2[n]);
                float w = uu * bm[n];
                eb[n] = fmaf(w, Pp[n], eb[n]);
                Pp[n] *= a;
                ef[n] = fmaf(a, ef[n], w);
            }
            pDu += CC; pBm += 4;
        }
        int i4 = ((b*RR + chunk)*CC + c)*4 + q;
        g_ef4[i4] = make_float4(ef[0],ef[1],ef[2],ef[3]);
        g_eb4[i4] = make_float4(eb[0],eb[1],eb[2],eb[3]);
        if (q == 0) g_rs[(b*RR + chunk)*CC + c] = rs;
    } else {
        float ec[NH];
        #pragma unroll
        for (int n = 0; n < NH; n++) ec[n] = 0.f;
        float cs = 0.f;
        const float2* pDu = g_du + ((size_t)(b*LL + chunk))*CC + c;
        const float4* pBm = g_Bm4 + (b*LL + chunk)*4 + q;
        #pragma unroll 4
        for (int h = 0; h < 64; h++) {
            float2 du = *pDu;
            float4 v = *pBm;
            float d = du.x, uu = du.y;
            cs += d;
            float bm[NH] = {v.x, v.y, v.z, v.w};
            #pragma unroll
            for (int n = 0; n < NH; n++) {
                float a = ex2f(d * A2[n]);
                float wv = uu * bm[n];
                ec[n] = fmaf(a, ec[n], wv);
            }
            pDu += 64*CC; pBm += 256;
        }
        int i4 = ((b*RR + chunk)*CC + c)*4 + q;
        g_ec4[i4] = make_float4(ec[0],ec[1],ec[2],ec[3]);
        if (q == 0) g_cs[(b*RR + chunk)*CC + c] = cs;
    }
}

// ---------------- mid: carry scans, smem-transposed + warp Kogge-Stone ----------------
__global__ void __launch_bounds__(256) k_mid_t() {
    __shared__ float2 tA[32][33];
    __shared__ float2 tB[32][33];
    __shared__ float rs_sm[2][64];

    int t = threadIdx.x;
    int warp = t >> 5, lane = t & 31;
    int which = blockIdx.y;
    int g0 = blockIdx.x * 32;
    int b = g0 / CN;
    int cn0 = g0 % CN;
    int cbase = cn0 >> 4;
    const unsigned FULL = 0xffffffffu;

    const float* grs = (which == 2) ? g_cs : g_rs;
    if (t < 128) {
        int r = t & 63, cl = t >> 6;
        rs_sm[cl][r] = grs[(b*RR + r)*CC + cbase + cl];
    }
    const float* eA = (which == 0) ? (const float*)g_ef4
                    : (which == 1) ? (const float*)g_eb4
                                   : (const float*)g_ec4;
    #pragma unroll
    for (int i = 0; i < 8; i++) {
        int r = warp*8 + i;
        size_t src = (size_t)(b*RR + r)*CN + cn0 + lane;
        ((float*)&tA[lane][0])[r] = eA[src];
        if (which == 1)
            ((float*)&tB[lane][0])[r] = ((const float*)g_ef4)[src];
    }
    __syncthreads();

    #pragma unroll
    for (int k = 0; k < 4; k++) {
        int cnl = warp*4 + k;
        float A2v = ((const float*)g_A4)[cn0 + cnl];
        int cl = cnl >> 4;

        if (which == 0) {
            float2 e = tA[cnl][lane];
            float e0 = e.x, e1 = e.y;
            float G0 = ex2f(A2v * rs_sm[cl][2*lane]);
            float G1 = ex2f(A2v * rs_sm[cl][2*lane+1]);
            float a  = G0 * G1;
            float bv = fmaf(G1, e0, e1);
            #pragma unroll
            for (int off = 1; off < 32; off <<= 1) {
                float pa = __shfl_up_sync(FULL, a, off);
                float pb = __shfl_up_sync(FULL, bv, off);
                if (lane >= off) { bv = fmaf(a, pb, bv); a *= pa; }
            }
            float xb = __shfl_up_sync(FULL, bv, 1);
            if (lane == 0) xb = 0.f;
            tA[cnl][lane] = make_float2(xb, fmaf(G0, xb, e0));
        } else {
            int slot = 31 - lane;
            float2 e = tA[cnl][slot];
            float e0 = e.y, e1 = e.x;
            float G0 = ex2f(A2v * rs_sm[cl][63 - 2*lane]);
            float G1 = ex2f(A2v * rs_sm[cl][62 - 2*lane]);
            float a  = G0 * G1;
            float bv = fmaf(G1, e0, e1);
            if (which == 1) {
                float2 e3 = tB[cnl][slot];
                float f0 = e3.y, f1 = e3.x;
                float b3 = fmaf(G1, f0, f1);
                float a2 = a;
                #pragma unroll
                for (int off = 1; off < 32; off <<= 1) {
                    float pa  = __shfl_up_sync(FULL, a2, off);
                    float pb2 = __shfl_up_sync(FULL, bv, off);
                    float pb3 = __shfl_up_sync(FULL, b3, off);
                    if (lane >= off) {
                        bv = fmaf(a2, pb2, bv);
                        b3 = fmaf(a2, pb3, b3);
                        a2 *= pa;
                    }
                }
                float xb2 = __shfl_up_sync(FULL, bv, 1);
                float xb3 = __shfl_up_sync(FULL, b3, 1);
                if (lane == 0) { xb2 = 0.f; xb3 = 0.f; }
                tA[cnl][slot] = make_float2(fmaf(G0, xb2, e0), xb2);
                tB[cnl][slot] = make_float2(fmaf(G0, xb3, f0), xb3);
            } else {
                #pragma unroll
                for (int off = 1; off < 32; off <<= 1) {
                    float pa = __shfl_up_sync(FULL, a, off);
                    float pb = __shfl_up_sync(FULL, bv, off);
                    if (lane >= off) { bv = fmaf(a, pb, bv); a *= pa; }
                }
                float xb = __shfl_up_sync(FULL, bv, 1);
                if (lane == 0) xb = 0.f;
                tA[cnl][slot] = make_float2(fmaf(G0, xb, e0), xb);
            }
        }
    }
    __syncthreads();

    float* oA = (which == 0) ? (float*)g_c14
              : (which == 1) ? (float*)g_c24
                             : (float*)g_c44;
    #pragma unroll
    for (int i = 0; i < 8; i++) {
        int r = warp*8 + i;
        size_t dst = (size_t)(b*RR + r)*CN + cn0 + lane;
        oA[dst] = ((float*)&tA[lane][0])[r];
        if (which == 1)
            ((float*)g_c34)[dst] = ((float*)&tB[lane][0])[r];
    }
}

// ---------------- pass2: local scans with carries, emit y ----------------
__global__ void __launch_bounds__(256) k_pass2() {
    int blk = blockIdx.x;
    int q = threadIdx.x & 3;

    if (blk < BB*RR*8) {
        int b = blk / (RR*8);
        int rem = blk % (RR*8);
        int chunk = rem >> 3;
        int cg = rem & 7;
        int warp = threadIdx.x >> 5;
        int wd = warp >> 2;                      // 0 = asc, 1 = desc
        int wi = warp & 3;
        int c = cg*32 + wi*8 + ((threadIdx.x & 31) >> 2);

        float A2[NH];
        {
            float4 a0 = g_A4[c*4 + q];
            A2[0]=a0.x; A2[1]=a0.y; A2[2]=a0.z; A2[3]=a0.w;
        }
        int i4 = ((b*RR + chunk)*CC + c)*4 + q;
        int pbase = chunk*64;

        if (wd == 0) {
            float h1[NH], h3[NH];
            {
                float4 v0 = g_c14[i4];
                h1[0]=v0.x; h1[1]=v0.y; h1[2]=v0.z; h1[3]=v0.w;
                float4 w0 = g_c34[i4];
                h3[0]=w0.x; h3[1]=w0.y; h3[2]=w0.z; h3[3]=w0.w;
            }
            size_t ia0 = ((size_t)(b*LL + pbase))*CC + c;
            const float2* pDu = g_du + ia0;
            const float4* pBm = g_Bm4 + (b*LL + pbase)*4 + q;
            const float4* pCm = g_Cm4 + (b*LL + pbase)*4 + q;
            float* pY = g_y13 + ia0;
            #pragma unroll 4
            for (int i = 0; i < 64; i++) {
                float2 du = *pDu;
                float4 v = *pBm;
                float4 u = *pCm;
                float bm[NH] = {v.x, v.y, v.z, v.w};
                float cm[NH] = {u.x, u.y, u.z, u.w};
                float y = 0.f;
                #pragma unroll
                for (int n = 0; n < NH; n++) {
                    float a = ex2f(du.x * A2[n]);
                    float w = du.y * bm[n];
                    h1[n] = fmaf(a, h1[n], w);
                    h3[n] = fmaf(a, h3[n], w);
                    y = fmaf(h1[n] + h3[n], cm[n], y);
                }
                y += __shfl_xor_sync(0xffffffffu, y, 1);
                y += __shfl_xor_sync(0xffffffffu, y, 2);
                if (q == 0) *pY = y;
                pDu += CC; pBm += 4; pCm += 4; pY += CC;
            }
        } else {
            float h2[NH];
            {
                float4 v0 = g_c24[i4];
                h2[0]=v0.x; h2[1]=v0.y; h2[2]=v0.z; h2[3]=v0.w;
            }
            size_t id0 = ((size_t)(b*LL + pbase + 63))*CC + c;
            const float2* pDu = g_du + id0;
            const float4* pBm = g_Bm4 + (b*LL + pbase + 63)*4 + q;
            const float4* pCm = g_Cm4 + (b*LL + pbase + 63)*4 + q;
            float* pY = g_y2 + id0;
            #pragma unroll 4
            for (int i = 0; i < 64; i++) {
                float2 du = *pDu;
                float4 v = *pBm;
                float4 u = *pCm;
                float bm[NH] = {v.x, v.y, v.z, v.w};
                float cm[NH] = {u.x, u.y, u.z, u.w};
                float y = 0.f;
                #pragma unroll
                for (int n = 0; n < NH; n++) {
                    float a = ex2f(du.x * A2[n]);
                    float w = du.y * bm[n];
                    h2[n] = fmaf(a, h2[n], w);
                    y = fmaf(h2[n], cm[n], y);
                }
                y += __shfl_xor_sync(0xffffffffu, y, 1);
                y += __shfl_xor_sync(0xffffffffu, y, 2);
                if (q == 0) *pY = y;
                pDu -= CC; pBm -= 4; pCm -= 4; pY -= CC;
            }
        }
    } else {
        int bid = blk - BB*RR*8;
        int b = bid / (RR*4);
        int rem = bid % (RR*4);
        int chunk = rem >> 2;                    // column index
        int cg = rem & 3;
        int c = cg*64 + (threadIdx.x >> 2);

        float A2[NH];
        {
            float4 a0 = g_A4[c*4 + q];
            A2[0]=a0.x; A2[1]=a0.y; A2[2]=a0.z; A2[3]=a0.w;
        }
        int i4 = ((b*RR + chunk)*CC + c)*4 + q;
        float h4[NH];
        {
            float4 v0 = g_c44[i4];
            h4[0]=v0.x; h4[1]=v0.y; h4[2]=v0.z; h4[3]=v0.w;
        }
        size_t i0 = ((size_t)(b*LL + chunk))*CC + c;
        const float2* pDu = g_du + i0;
        const float4* pBm = g_Bm4 + (b*LL + chunk)*4 + q;
        const float4* pCm = g_Cm4 + (b*LL + chunk)*4 + q;
        float* pY = g_y4 + i0;
        #pragma unroll 4
        for (int h = 0; h < 64; h++) {
            float2 du = *pDu;
            float4 v = *pBm;
            float4 u = *pCm;
            float bm[NH] = {v.x, v.y, v.z, v.w};
            float cm[NH] = {u.x, u.y, u.z, u.w};
            float y = 0.f;
            #pragma unroll
            for (int n = 0; n < NH; n++) {
                float a = ex2f(du.x * A2[n]);
                float wv = du.y * bm[n];
                h4[n] = fmaf(a, h4[n], wv);
                y = fmaf(h4[n], cm[n], y);
            }
            y += __shfl_xor_sync(0xffffffffu, y, 1);
            y += __shfl_xor_sync(0xffffffffu, y, 2);
            if (q == 0) *pY = y;
            pDu += 64*CC; pBm += 256; pCm += 256; pY += 64*CC;
        }
    }
}

// ---------------- final: combine 3 buffers, add x*D, transpose ----------------
__global__ void k_final(const float* __restrict__ F,
                        const float* __restrict__ Dv,
                        float* __restrict__ out)
{
    __shared__ float tile[32][33];
    int p0 = blockIdx.x * 32;
    int c0 = blockIdx.y * 32;
    int b = blockIdx.z;
    int tx = threadIdx.x, ty = threadIdx.y;   // (32, 8)
    #pragma unroll
    for (int i = 0; i < 4; i++) {
        int p = p0 + ty + i*8;
        size_t idx = ((size_t)(b*LL + p))*CC + c0 + tx;
        tile[ty + i*8][tx] = g_y13[idx] + g_y2[idx] + g_y4[idx];
    }
    __syncthreads();
    #pragma unroll
    for (int i = 0; i < 4; i++) {
        int cc = c0 + ty + i*8;
        int p = p0 + tx;
        size_t o = (size_t)b*CC*LL + (size_t)cc*LL + p;
        out[o] = 0.25f * tile[tx][ty + i*8] + F[o] * Dv[cc];
    }
}

// ---------------- launch ----------------
extern "C" void kernel_launch(void* const* d_in, const int* in_sizes, int n_in,
                              void* d_out, int out_size) {
    const float* F     = (const float*)d_in[0];
    const float* A_log = (const float*)d_in[1];
    const float* Dv    = (const float*)d_in[2];
    const float* Wd    = (const float*)d_in[3];
    const float* bd    = (const float*)d_in[4];
    const float* WB    = (const float*)d_in[5];
    const float* WC    = (const float*)d_in[6];
    float* out = (float*)d_out;

    {
        dim3 gd(BB*LL/128, 5);
        k_gemm_tc<<<gd, 256>>>(F, Wd, bd, WB, WC, A_log);
    }
    k_pass1<<<2*BB*RR*4, 256>>>();
    k_mid_t<<<dim3(BB*CN/32, 3), 256>>>();
    k_pass2<<<BB*RR*8 + BB*RR*4, 256>>>();
    k_final<<<dim3(LL/32, CC/32, BB), dim3(32, 8)>>>(F, Dv, out);
}

// round 16
// speedup vs baseline: 1.0854x; 1.0171x over previous
#include <cuda_runtime.h>
#include <cuda_bf16.h>

#define BB 2
#define CC 256
#define LL 4096
#define NN 16
#define RR 64
#define NH 4    // n-values per thread (n split across lane quads)
#define CN (CC*NN)

// ---------------- static device scratch (no allocations) ----------------
__device__ float4 g_A4   [CC*NN/4];          // A2 = -exp(A_log)*log2(e), (c,n)
__device__ float2 g_du   [BB*LL*CC];         // (delta, delta*x) packed
__device__ float4 g_Bm4  [BB*LL*NN/4];       // (b,p,n)
__device__ float4 g_Cm4  [BB*LL*NN/4];
__device__ float  g_rs   [BB*RR*CC];         // row delta sums
__device__ float  g_cs   [BB*RR*CC];         // col delta sums
__device__ float4 g_ef4  [BB*RR*CC*NN/4];    // row fwd local end states
__device__ float4 g_eb4  [BB*RR*CC*NN/4];    // row bwd local end states
__device__ float4 g_ec4  [BB*RR*CC*NN/4];    // col fwd local end states
__device__ float4 g_c14  [BB*RR*CC*NN/4];    // carries per chunk, dir 1..4
__device__ float4 g_c24  [BB*RR*CC*NN/4];
__device__ float4 g_c34  [BB*RR*CC*NN/4];
__device__ float4 g_c44  [BB*RR*CC*NN/4];
__device__ float  g_y13  [BB*LL*CC];         // y1+y3
__device__ float  g_y2   [BB*LL*CC];         // y2
__device__ float  g_y4   [BB*LL*CC];         // y4

__device__ __forceinline__ float ex2f(float x) {
    float r; asm("ex2.approx.f32 %0, %1;" : "=f"(r) : "f"(x)); return r;
}

__device__ __forceinline__ unsigned cvt_tf32(float x) {
    unsigned h; asm("cvt.rna.tf32.f32 %0, %1;" : "=r"(h) : "f"(x)); return h;
}
__device__ __forceinline__ void split_tf32(float x, unsigned& hi, unsigned& lo) {
    unsigned h; asm("cvt.rna.tf32.f32 %0, %1;" : "=r"(h) : "f"(x));
    float hf = __uint_as_float(h);
    float l = x - hf;
    unsigned lw; asm("cvt.rna.tf32.f32 %0, %1;" : "=r"(lw) : "f"(l));
    hi = h; lo = lw;
}

#define MMA8(acc, a, bq) asm volatile( \
  "mma.sync.aligned.m16n8k8.row.col.f32.tf32.tf32.f32 " \
  "{%0,%1,%2,%3},{%4,%5,%6,%7},{%8,%9},{%0,%1,%2,%3};\n" \
  : "+f"(acc[0]),"+f"(acc[1]),"+f"(acc[2]),"+f"(acc[3]) \
  : "r"(a[0]),"r"(a[1]),"r"(a[2]),"r"(a[3]), "r"(bq[0]),"r"(bq[1]))

__device__ __forceinline__ float softplusf(float xw) {
    return (xw > 0.f) ? xw + log1pf(__expf(-xw)) : log1pf(__expf(xw));
}

// ---------------- fused GEMM (tensor cores, tf32, B-side compensated) ----------------
__global__ void __launch_bounds__(256, 2) k_gemm_tc(
    const float* __restrict__ F,
    const float* __restrict__ Wd,
    const float* __restrict__ bd,
    const float* __restrict__ WB,
    const float* __restrict__ WC,
    const float* __restrict__ A_log)
{
    __shared__ float As[2][16][132];
    __shared__ float Bs[2][16][68];
    int t = threadIdx.x;
    bool isBC = (blockIdx.y == 4);
    if (isBC && blockIdx.x < 16) {
        int i = blockIdx.x * 256 + t;
        ((float*)g_A4)[i] = -expf(A_log[i]) * 1.4426950408889634f;
    }
    int m0 = blockIdx.x * 128;
    int n0 = blockIdx.y * 64;
    int b = m0 / LL;
    int pbase = m0 % LL;
    int warp = t >> 5, lane = t & 31;
    int wm = warp >> 1, wn = warp & 1;
    int lr = lane >> 2, lc = lane & 3;

    const float* Fb = F + (size_t)b*CC*LL + pbase;
    float acc[2][4][4] = {};

    auto stage = [&](int chunk, int buf) {
        int k0 = chunk * 16;
        #pragma unroll
        for (int i = 0; i < 2; i++) {
            int s = t + i*256;
            int k = s >> 5, m4 = (s & 31) << 2;
            unsigned dst = (unsigned)__cvta_generic_to_shared(&As[buf][k][m4]);
            const float* src = Fb + (size_t)(k0+k)*LL + m4;
            asm volatile("cp.async.cg.shared.global [%0], [%1], 16;\n" :: "r"(dst), "l"(src));
        }
        {
            int s = t;
            int k = s >> 4, n4 = (s & 15) << 2;
            unsigned dst = (unsigned)__cvta_generic_to_shared(&Bs[buf][k][n4]);
            if (!isBC) {
                const float* src = Wd + (size_t)(k0+k)*CC + n0 + n4;
                asm volatile("cp.async.cg.shared.global [%0], [%1], 16;\n" :: "r"(dst), "l"(src));
            } else {
                const float* src = (n4 < 16) ? (WB + (size_t)(k0+k)*16 + n4)
                                 : (n4 < 32) ? (WC + (size_t)(k0+k)*16 + (n4-16))
                                             : WB;
                int sz = (n4 < 32) ? 16 : 0;
                asm volatile("cp.async.cg.shared.global [%0], [%1], 16, %2;\n"
                             :: "r"(dst), "l"(src), "r"(sz));
            }
        }
        asm volatile("cp.async.commit_group;\n");
    };

    stage(0, 0);
    for (int chunk = 0; chunk < 16; chunk++) {
        int buf = chunk & 1;
        if (chunk < 15) {
            stage(chunk+1, buf^1);
            asm volatile("cp.async.wait_group 1;\n");
        } else {
            asm volatile("cp.async.wait_group 0;\n");
        }
        __syncthreads();
        #pragma unroll
        for (int kk = 0; kk < 16; kk += 8) {
            unsigned ah[2][4], bh[4][2], bl[4][2];
            #pragma unroll
            for (int mt = 0; mt < 2; mt++) {
                int row = wm*32 + mt*16 + lr;
                ah[mt][0] = cvt_tf32(As[buf][kk+lc][row]);
                ah[mt][1] = cvt_tf32(As[buf][kk+lc][row+8]);
                ah[mt][2] = cvt_tf32(As[buf][kk+4+lc][row]);
                ah[mt][3] = cvt_tf32(As[buf][kk+4+lc][row+8]);
            }
            #pragma unroll
            for (int nt = 0; nt < 4; nt++) {
                int n = wn*32 + nt*8 + lr;
                split_tf32(Bs[buf][kk+lc][n],   bh[nt][0], bl[nt][0]);
                split_tf32(Bs[buf][kk+4+lc][n], bh[nt][1], bl[nt][1]);
            }
            #pragma unroll
            for (int mt = 0; mt < 2; mt++)
                #pragma unroll
                for (int nt = 0; nt < 4; nt++) {
                    MMA8(acc[mt][nt], ah[mt], bh[nt]);
                    MMA8(acc[mt][nt], ah[mt], bl[nt]);
                }
        }
        __syncthreads();
    }

    if (!isBC) {
        #pragma unroll
        for (int mt = 0; mt < 2; mt++) {
            int m_lo = wm*32 + mt*16 + lr;
            #pragma unroll
            for (int nt = 0; nt < 4; nt++) {
                int n = n0 + wn*32 + nt*8 + lc*2;
                float b0 = bd[n], b1 = bd[n+1];
                #pragma unroll
                for (int h = 0; h < 2; h++) {
                    int m = m_lo + h*8;
                    size_t mg = (size_t)m0 + m;
                    float sp0 = softplusf(acc[mt][nt][h*2+0] + b0);
                    float sp1 = softplusf(acc[mt][nt][h*2+1] + b1);
                    float x0 = Fb[(size_t)n*LL + m];
                    float x1 = Fb[(size_t)(n+1)*LL + m];
                    g_du[mg*CC + n]     = make_float2(sp0, sp0*x0);
                    g_du[mg*CC + n + 1] = make_float2(sp1, sp1*x1);
                }
            }
        }
    } else {
        float* gBm = (float*)g_Bm4;
        float* gCm = (float*)g_Cm4;
        #pragma unroll
        for (int mt = 0; mt < 2; mt++) {
            int m_lo = wm*32 + mt*16 + lr;
            #pragma unroll
            for (int nt = 0; nt < 4; nt++) {
                int nl = wn*32 + nt*8 + lc*2;
                if (nl >= 32) continue;
                #pragma unroll
                for (int h = 0; h < 2; h++) {
                    int m = m_lo + h*8;
                    size_t mg = (size_t)m0 + m;
                    float v0 = acc[mt][nt][h*2+0];
                    float v1 = acc[mt][nt][h*2+1];
                    if (nl < 16) {
                        gBm[mg*NN + nl]     = v0;
                        gBm[mg*NN + nl + 1] = v1;
                    } else {
                        gCm[mg*NN + nl - 16] = v0;
                        gCm[mg*NN + nl - 15] = v1;
                    }
                }
            }
        }
    }
}

// ---------------- pass1: per-chunk local end states + delta sums ----------------
__global__ void __launch_bounds__(256) k_pass1() {
    int blk = blockIdx.x;
    bool isCol = blk >= BB*RR*4;
    int bid = isCol ? blk - BB*RR*4 : blk;
    int b = bid / (RR*4);
    int rem = bid % (RR*4);
    int chunk = rem >> 2;
    int cg = rem & 3;
    int q = threadIdx.x & 3;
    int c = cg*64 + (threadIdx.x >> 2);

    float A2[NH];
    {
        float4 a0 = g_A4[c*4 + q];
        A2[0]=a0.x; A2[1]=a0.y; A2[2]=a0.z; A2[3]=a0.w;
    }

    if (!isCol) {
        float ef[NH], eb[NH], Pp[NH];
        #pragma unroll
        for (int n = 0; n < NH; n++) { ef[n]=0.f; eb[n]=0.f; Pp[n]=1.f; }
        float rs = 0.f;
        int pbase = chunk*64;
        const float2* pDu = g_du + ((size_t)(b*LL + pbase))*CC + c;
        const float4* pBm = g_Bm4 + (b*LL + pbase)*4 + q;
        #pragma unroll 4
        for (int ts = 0; ts < 64; ts++) {
            float2 du = *pDu;
            float4 v = *pBm;
            float d = du.x, uu = du.y;
            rs += d;
            float bm[NH] = {v.x, v.y, v.z, v.w};
            #pragma unroll
            for (int n = 0; n < NH; n++) {
                float a = ex2f(d * A2[n]);
                float w = uu * bm[n];
                eb[n] = fmaf(w, Pp[n], eb[n]);
                Pp[n] *= a;
                ef[n] = fmaf(a, ef[n], w);
            }
            pDu += CC; pBm += 4;
        }
        int i4 = ((b*RR + chunk)*CC + c)*4 + q;
        g_ef4[i4] = make_float4(ef[0],ef[1],ef[2],ef[3]);
        g_eb4[i4] = make_float4(eb[0],eb[1],eb[2],eb[3]);
        if (q == 0) g_rs[(b*RR + chunk)*CC + c] = rs;
    } else {
        float ec[NH];
        #pragma unroll
        for (int n = 0; n < NH; n++) ec[n] = 0.f;
        float cs = 0.f;
        const float2* pDu = g_du + ((size_t)(b*LL + chunk))*CC + c;
        const float4* pBm = g_Bm4 + (b*LL + chunk)*4 + q;
        #pragma unroll 4
        for (int h = 0; h < 64; h++) {
            float2 du = *pDu;
            float4 v = *pBm;
            float d = du.x, uu = du.y;
            cs += d;
            float bm[NH] = {v.x, v.y, v.z, v.w};
            #pragma unroll
            for (int n = 0; n < NH; n++) {
                float a = ex2f(d * A2[n]);
                float wv = uu * bm[n];
                ec[n] = fmaf(a, ec[n], wv);
            }
            pDu += 64*CC; pBm += 256;
        }
        int i4 = ((b*RR + chunk)*CC + c)*4 + q;
        g_ec4[i4] = make_float4(ec[0],ec[1],ec[2],ec[3]);
        if (q == 0) g_cs[(b*RR + chunk)*CC + c] = cs;
    }
}

// ---------------- mid: carry scans, smem-transposed + warp Kogge-Stone ----------------
__global__ void __launch_bounds__(256) k_mid_t() {
    __shared__ float2 tA[32][33];
    __shared__ float2 tB[32][33];
    __shared__ float rs_sm[2][64];

    int t = threadIdx.x;
    int warp = t >> 5, lane = t & 31;
    int which = blockIdx.y;
    int g0 = blockIdx.x * 32;
    int b = g0 / CN;
    int cn0 = g0 % CN;
    int cbase = cn0 >> 4;
    const unsigned FULL = 0xffffffffu;

    const float* grs = (which == 2) ? g_cs : g_rs;
    if (t < 128) {
        int r = t & 63, cl = t >> 6;
        rs_sm[cl][r] = grs[(b*RR + r)*CC + cbase + cl];
    }
    const float* eA = (which == 0) ? (const float*)g_ef4
                    : (which == 1) ? (const float*)g_eb4
                                   : (const float*)g_ec4;
    #pragma unroll
    for (int i = 0; i < 8; i++) {
        int r = warp*8 + i;
        size_t src = (size_t)(b*RR + r)*CN + cn0 + lane;
        ((float*)&tA[lane][0])[r] = eA[src];
        if (which == 1)
            ((float*)&tB[lane][0])[r] = ((const float*)g_ef4)[src];
    }
    __syncthreads();

    #pragma unroll
    for (int k = 0; k < 4; k++) {
        int cnl = warp*4 + k;
        float A2v = ((const float*)g_A4)[cn0 + cnl];
        int cl = cnl >> 4;

        if (which == 0) {
            float2 e = tA[cnl][lane];
            float e0 = e.x, e1 = e.y;
            float G0 = ex2f(A2v * rs_sm[cl][2*lane]);
            float G1 = ex2f(A2v * rs_sm[cl][2*lane+1]);
            float a  = G0 * G1;
            float bv = fmaf(G1, e0, e1);
            #pragma unroll
            for (int off = 1; off < 32; off <<= 1) {
                float pa = __shfl_up_sync(FULL, a, off);
                float pb = __shfl_up_sync(FULL, bv, off);
                if (lane >= off) { bv = fmaf(a, pb, bv); a *= pa; }
            }
            float xb = __shfl_up_sync(FULL, bv, 1);
            if (lane == 0) xb = 0.f;
            tA[cnl][lane] = make_float2(xb, fmaf(G0, xb, e0));
        } else {
            int slot = 31 - lane;
            float2 e = tA[cnl][slot];
            float e0 = e.y, e1 = e.x;
            float G0 = ex2f(A2v * rs_sm[cl][63 - 2*lane]);
            float G1 = ex2f(A2v * rs_sm[cl][62 - 2*lane]);
            float a  = G0 * G1;
            float bv = fmaf(G1, e0, e1);
            if (which == 1) {
                float2 e3 = tB[cnl][slot];
                float f0 = e3.y, f1 = e3.x;
                float b3 = fmaf(G1, f0, f1);
                float a2 = a;
                #pragma unroll
                for (int off = 1; off < 32; off <<= 1) {
                    float pa  = __shfl_up_sync(FULL, a2, off);
                    float pb2 = __shfl_up_sync(FULL, bv, off);
                    float pb3 = __shfl_up_sync(FULL, b3, off);
                    if (lane >= off) {
                        bv = fmaf(a2, pb2, bv);
                        b3 = fmaf(a2, pb3, b3);
                        a2 *= pa;
                    }
                }
                float xb2 = __shfl_up_sync(FULL, bv, 1);
                float xb3 = __shfl_up_sync(FULL, b3, 1);
                if (lane == 0) { xb2 = 0.f; xb3 = 0.f; }
                tA[cnl][slot] = make_float2(fmaf(G0, xb2, e0), xb2);
                tB[cnl][slot] = make_float2(fmaf(G0, xb3, f0), xb3);
            } else {
                #pragma unroll
                for (int off = 1; off < 32; off <<= 1) {
                    float pa = __shfl_up_sync(FULL, a, off);
                    float pb = __shfl_up_sync(FULL, bv, off);
                    if (lane >= off) { bv = fmaf(a, pb, bv); a *= pa; }
                }
                float xb = __shfl_up_sync(FULL, bv, 1);
                if (lane == 0) xb = 0.f;
                tA[cnl][slot] = make_float2(fmaf(G0, xb, e0), xb);
            }
        }
    }
    __syncthreads();

    float* oA = (which == 0) ? (float*)g_c14
              : (which == 1) ? (float*)g_c24
                             : (float*)g_c44;
    #pragma unroll
    for (int i = 0; i < 8; i++) {
        int r = warp*8 + i;
        size_t dst = (size_t)(b*RR + r)*CN + cn0 + lane;
        oA[dst] = ((float*)&tA[lane][0])[r];
        if (which == 1)
            ((float*)g_c34)[dst] = ((float*)&tB[lane][0])[r];
    }
}

// ---------------- pass2: local scans with carries, emit y ----------------
// Row asc warps use fused h13 = h1 + h3 state: h13' = a*h13 + 2w, y1+y3 = h13.cm
__global__ void __launch_bounds__(256) k_pass2() {
    int blk = blockIdx.x;
    int q = threadIdx.x & 3;

    if (blk < BB*RR*8) {
        int b = blk / (RR*8);
        int rem = blk % (RR*8);
        int chunk = rem >> 3;
        int cg = rem & 7;
        int warp = threadIdx.x >> 5;
        int wd = warp >> 2;                      // 0 = asc, 1 = desc
        int wi = warp & 3;
        int c = cg*32 + wi*8 + ((threadIdx.x & 31) >> 2);

        float A2[NH];
        {
            float4 a0 = g_A4[c*4 + q];
            A2[0]=a0.x; A2[1]=a0.y; A2[2]=a0.z; A2[3]=a0.w;
        }
        int i4 = ((b*RR + chunk)*CC + c)*4 + q;
        int pbase = chunk*64;

        if (wd == 0) {
            float h13[NH];
            {
                float4 v0 = g_c14[i4];
                float4 w0 = g_c34[i4];
                h13[0] = v0.x + w0.x; h13[1] = v0.y + w0.y;
                h13[2] = v0.z + w0.z; h13[3] = v0.w + w0.w;
            }
            size_t ia0 = ((size_t)(b*LL + pbase))*CC + c;
            const float2* pDu = g_du + ia0;
            const float4* pBm = g_Bm4 + (b*LL + pbase)*4 + q;
            const float4* pCm = g_Cm4 + (b*LL + pbase)*4 + q;
            float* pY = g_y13 + ia0;
            #pragma unroll 4
            for (int i = 0; i < 64; i++) {
                float2 du = *pDu;
                float4 v = *pBm;
                float4 u = *pCm;
                float uu2 = du.y + du.y;
                float bm[NH] = {v.x, v.y, v.z, v.w};
                float cm[NH] = {u.x, u.y, u.z, u.w};
                float y = 0.f;
                #pragma unroll
                for (int n = 0; n < NH; n++) {
                    float a = ex2f(du.x * A2[n]);
                    float w2 = uu2 * bm[n];
                    h13[n] = fmaf(a, h13[n], w2);
                    y = fmaf(h13[n], cm[n], y);
                }
                y += __shfl_xor_sync(0xffffffffu, y, 1);
                y += __shfl_xor_sync(0xffffffffu, y, 2);
                if (q == 0) *pY = y;
                pDu += CC; pBm += 4; pCm += 4; pY += CC;
            }
        } else {
            float h2[NH];
            {
                float4 v0 = g_c24[i4];
                h2[0]=v0.x; h2[1]=v0.y; h2[2]=v0.z; h2[3]=v0.w;
            }
            size_t id0 = ((size_t)(b*LL + pbase + 63))*CC + c;
            const float2* pDu = g_du + id0;
            const float4* pBm = g_Bm4 + (b*LL + pbase + 63)*4 + q;
            const float4* pCm = g_Cm4 + (b*LL + pbase + 63)*4 + q;
            float* pY = g_y2 + id0;
            #pragma unroll 4
            for (int i = 0; i < 64; i++) {
                float2 du = *pDu;
                float4 v = *pBm;
                float4 u = *pCm;
                float bm[NH] = {v.x, v.y, v.z, v.w};
                float cm[NH] = {u.x, u.y, u.z, u.w};
                float y = 0.f;
                #pragma unroll
                for (int n = 0; n < NH; n++) {
                    float a = ex2f(du.x * A2[n]);
                    float w = du.y * bm[n];
                    h2[n] = fmaf(a, h2[n], w);
                    y = fmaf(h2[n], cm[n], y);
                }
                y += __shfl_xor_sync(0xffffffffu, y, 1);
                y += __shfl_xor_sync(0xffffffffu, y, 2);
                if (q == 0) *pY = y;
                pDu -= CC; pBm -= 4; pCm -= 4; pY -= CC;
            }
        }
    } else {
        int bid = blk - BB*RR*8;
        int b = bid / (RR*4);
        int rem = bid % (RR*4);
        int chunk = rem >> 2;                    // column index
        int cg = rem & 3;
        int c = cg*64 + (threadIdx.x >> 2);

        float A2[NH];
        {
            float4 a0 = g_A4[c*4 + q];
            A2[0]=a0.x; A2[1]=a0.y; A2[2]=a0.z; A2[3]=a0.w;
        }
        int i4 = ((b*RR + chunk)*CC + c)*4 + q;
        float h4[NH];
        {
            float4 v0 = g_c44[i4];
            h4[0]=v0.x; h4[1]=v0.y; h4[2]=v0.z; h4[3]=v0.w;
        }
        size_t i0 = ((size_t)(b*LL + chunk))*CC + c;
        const float2* pDu = g_du + i0;
        const float4* pBm = g_Bm4 + (b*LL + chunk)*4 + q;
        const float4* pCm = g_Cm4 + (b*LL + chunk)*4 + q;
        float* pY = g_y4 + i0;
        #pragma unroll 4
        for (int h = 0; h < 64; h++) {
            float2 du = *pDu;
            float4 v = *pBm;
            float4 u = *pCm;
            float bm[NH] = {v.x, v.y, v.z, v.w};
            float cm[NH] = {u.x, u.y, u.z, u.w};
            float y = 0.f;
            #pragma unroll
            for (int n = 0; n < NH; n++) {
                float a = ex2f(du.x * A2[n]);
                float wv = du.y * bm[n];
                h4[n] = fmaf(a, h4[n], wv);
                y = fmaf(h4[n], cm[n], y);
            }
            y += __shfl_xor_sync(0xffffffffu, y, 1);
            y += __shfl_xor_sync(0xffffffffu, y, 2);
            if (q == 0) *pY = y;
            pDu += 64*CC; pBm += 256; pCm += 256; pY += 64*CC;
        }
    }
}

// ---------------- final: combine 3 buffers, add x*D, transpose ----------------
__global__ void k_final(const float* __restrict__ F,
                        const float* __restrict__ Dv,
                        float* __restrict__ out)
{
    __shared__ float tile[32][33];
    int p0 = blockIdx.x * 32;
    int c0 = blockIdx.y * 32;
    int b = blockIdx.z;
    int tx = threadIdx.x, ty = threadIdx.y;   // (32, 8)
    #pragma unroll
    for (int i = 0; i < 4; i++) {
        int p = p0 + ty + i*8;
        size_t idx = ((size_t)(b*LL + p))*CC + c0 + tx;
        tile[ty + i*8][tx] = g_y13[idx] + g_y2[idx] + g_y4[idx];
    }
    __syncthreads();
    #pragma unroll
    for (int i = 0; i < 4; i++) {
        int cc = c0 + ty + i*8;
        int p = p0 + tx;
        size_t o = (size_t)b*CC*LL + (size_t)cc*LL + p;
        out[o] = 0.25f * tile[tx][ty + i*8] + F[o] * Dv[cc];
    }
}

// ---------------- launch ----------------
extern "C" void kernel_launch(void* const* d_in, const int* in_sizes, int n_in,
                              void* d_out, int out_size) {
    const float* F     = (const float*)d_in[0];
    const float* A_log = (const float*)d_in[1];
    const float* Dv    = (const float*)d_in[2];
    const float* Wd    = (const float*)d_in[3];
    const float* bd    = (const float*)d_in[4];
    const float* WB    = (const float*)d_in[5];
    const float* WC    = (const float*)d_in[6];
    float* out = (float*)d_out;

    {
        dim3 gd(BB*LL/128, 5);
        k_gemm_tc<<<gd, 256>>>(F, Wd, bd, WB, WC, A_log);
    }
    k_pass1<<<2*BB*RR*4, 256>>>();
    k_mid_t<<<dim3(BB*CN/32, 3), 256>>>();
    k_pass2<<<BB*RR*8 + BB*RR*4, 256>>>();
    k_final<<<dim3(LL/32, CC/32, BB), dim3(32, 8)>>>(F, Dv, out);
}